// round 1
// baseline (speedup 1.0000x reference)
#include <cuda_runtime.h>
#include <math.h>

// ---------------- problem constants ----------------
#define LSEQ   4096
#define DM     256
#define DI     512          // D_INNER
#define DS     16           // D_STATE
#define DTR    16           // DT_RANK
#define NXP    48           // DT_RANK + 2*D_STATE
#define DCONV  4
#define NC     64           // scan chunks
#define CLEN   64           // steps per chunk (NC*CLEN == LSEQ)
#define LN_EPS 1e-5f

// ---------------- device scratch (no allocations allowed) ----------------
__device__ float g_t0  [LSEQ*DM];        // adj @ x
__device__ float g_h1  [LSEQ*DM];        // relu(t0 @ gcn_w + b)
__device__ float g_hln [LSEQ*DM];        // layernorm output
__device__ float g_xz  [LSEQ*2*DI];      // h @ w_in
__device__ float g_u   [LSEQ*DI];        // silu(conv(xc))
__device__ float g_dbc [LSEQ*NXP];       // u @ w_xp
__device__ float g_dt  [LSEQ*DI];        // softplus(dbc[:, :16] @ w_dt + b_dt)
__device__ float g_cP  [NC*DI*DS];       // chunk carry: prod(a)
__device__ float g_cS  [NC*DI*DS];       // chunk carry: scan sum
__device__ float g_hin [NC*DI*DS];       // per-chunk initial state
__device__ float g_yg  [LSEQ*DI];        // gated y (input to out proj)

// ---------------- generic FP32 SGEMM: C = A[MxK] * B[KxN] (+bias, relu) ----------------
// BM=128, BN=64, BK=16, 256 threads, 8x4 per-thread tile.
// Requires M%128==0, N%64==0, K%16==0 (true for all uses here).
template<bool BIAS_RELU>
__global__ __launch_bounds__(256)
void sgemm_k(const float* __restrict__ A, const float* __restrict__ B,
             const float* __restrict__ bias, float* __restrict__ C,
             int M, int N, int K)
{
    __shared__ float As[16][128];
    __shared__ float Bs[16][64];

    const int tid = threadIdx.x;
    const int bx  = blockIdx.x;   // N tile
    const int by  = blockIdx.y;   // M tile

    const float* Ab = A + (size_t)by * 128 * K;
    const float* Bb = B + bx * 64;

    const int ty = tid >> 4;      // 0..15 -> rows ty*8..ty*8+7
    const int tx = tid & 15;      // 0..15 -> cols tx*4..tx*4+3

    const int a_row = tid >> 2;          // 0..63 (and +64)
    const int a_k4  = (tid & 3) * 4;
    const int b_row = tid >> 4;          // 0..15
    const int b_c4  = (tid & 15) * 4;

    float acc[8][4];
#pragma unroll
    for (int i = 0; i < 8; i++)
#pragma unroll
        for (int j = 0; j < 4; j++) acc[i][j] = 0.f;

    for (int k0 = 0; k0 < K; k0 += 16) {
        float4 av0 = *(const float4*)(Ab + (size_t)a_row        * K + k0 + a_k4);
        float4 av1 = *(const float4*)(Ab + (size_t)(a_row + 64) * K + k0 + a_k4);
        float4 bv  = *(const float4*)(Bb + (size_t)(k0 + b_row) * N + b_c4);

        As[a_k4 + 0][a_row] = av0.x; As[a_k4 + 1][a_row] = av0.y;
        As[a_k4 + 2][a_row] = av0.z; As[a_k4 + 3][a_row] = av0.w;
        As[a_k4 + 0][a_row + 64] = av1.x; As[a_k4 + 1][a_row + 64] = av1.y;
        As[a_k4 + 2][a_row + 64] = av1.z; As[a_k4 + 3][a_row + 64] = av1.w;
        *(float4*)&Bs[b_row][b_c4] = bv;
        __syncthreads();

#pragma unroll
        for (int kk = 0; kk < 16; kk++) {
            float a[8], b[4];
#pragma unroll
            for (int i = 0; i < 8; i++) a[i] = As[kk][ty * 8 + i];
#pragma unroll
            for (int j = 0; j < 4; j++) b[j] = Bs[kk][tx * 4 + j];
#pragma unroll
            for (int i = 0; i < 8; i++)
#pragma unroll
                for (int j = 0; j < 4; j++) acc[i][j] += a[i] * b[j];
        }
        __syncthreads();
    }

    const int col0 = bx * 64 + tx * 4;
    float b4[4];
    if (BIAS_RELU) {
#pragma unroll
        for (int j = 0; j < 4; j++) b4[j] = bias[col0 + j];
    }
#pragma unroll
    for (int i = 0; i < 8; i++) {
        const int row = by * 128 + ty * 8 + i;
        float4 o;
        if (BIAS_RELU) {
            o.x = fmaxf(acc[i][0] + b4[0], 0.f);
            o.y = fmaxf(acc[i][1] + b4[1], 0.f);
            o.z = fmaxf(acc[i][2] + b4[2], 0.f);
            o.w = fmaxf(acc[i][3] + b4[3], 0.f);
        } else {
            o.x = acc[i][0]; o.y = acc[i][1]; o.z = acc[i][2]; o.w = acc[i][3];
        }
        *(float4*)(C + (size_t)row * N + col0) = o;
    }
}

// ---------------- layernorm over D_MODEL=256, one block per row ----------------
__global__ __launch_bounds__(256)
void ln_k(const float* __restrict__ h1, const float* __restrict__ g,
          const float* __restrict__ b, float* __restrict__ out)
{
    const int row = blockIdx.x;
    const int tid = threadIdx.x;
    float v = h1[(size_t)row * DM + tid];
    float s = v, s2 = v * v;
#pragma unroll
    for (int o = 16; o; o >>= 1) {
        s  += __shfl_xor_sync(0xffffffffu, s,  o);
        s2 += __shfl_xor_sync(0xffffffffu, s2, o);
    }
    __shared__ float ws[8], ws2[8];
    if ((tid & 31) == 0) { ws[tid >> 5] = s; ws2[tid >> 5] = s2; }
    __syncthreads();
    float ts = 0.f, ts2 = 0.f;
#pragma unroll
    for (int i = 0; i < 8; i++) { ts += ws[i]; ts2 += ws2[i]; }
    const float mu  = ts * (1.f / DM);
    const float var = ts2 * (1.f / DM) - mu * mu;
    const float r   = rsqrtf(var + LN_EPS);
    out[(size_t)row * DM + tid] = (v - mu) * r * g[tid] + b[tid];
}

// ---------------- depthwise conv (width 4, causal) + silu ----------------
__global__ __launch_bounds__(256)
void conv_silu_k(const float* __restrict__ xz, const float* __restrict__ cw,
                 const float* __restrict__ cb, float* __restrict__ u)
{
    const int idx = blockIdx.x * 256 + threadIdx.x;   // over LSEQ*DI
    const int l = idx >> 9, d = idx & (DI - 1);
    float s = cb[d];
#pragma unroll
    for (int k = 0; k < DCONV; k++) {
        const int ls = l - (DCONV - 1) + k;
        if (ls >= 0) s += xz[(size_t)ls * (2 * DI) + d] * cw[d * DCONV + k];
    }
    const float sig = 1.f / (1.f + __expf(-s));
    u[idx] = s * sig;
}

// ---------------- dbc = u @ w_xp  (4096x512 @ 512x48), 8 rows per block ----------------
__global__ __launch_bounds__(384)
void dbc_k(const float* __restrict__ u, const float* __restrict__ wxp,
           float* __restrict__ dbc)
{
    __shared__ float us[8][DI + 1];   // +1 pad to kill bank conflicts
    const int tid = threadIdx.x;
    const int l0 = blockIdx.x * 8;
    for (int i = tid; i < 8 * DI; i += 384)
        us[i >> 9][i & (DI - 1)] = u[(size_t)l0 * DI + i];
    __syncthreads();
    const int j = tid % NXP, r = tid / NXP;
    const float* ur = us[r];
    float acc = 0.f;
#pragma unroll 8
    for (int k = 0; k < DI; k++) acc += ur[k] * wxp[k * NXP + j];
    dbc[(size_t)(l0 + r) * NXP + j] = acc;
}

// ---------------- dt = softplus(dbc[:, :16] @ w_dt + b_dt) ----------------
__global__ __launch_bounds__(256)
void dt_k(const float* __restrict__ dbc, const float* __restrict__ wdt,
          const float* __restrict__ bdt, float* __restrict__ dt)
{
    const int idx = blockIdx.x * 256 + threadIdx.x;   // over LSEQ*DI
    const int l = idx >> 9, d = idx & (DI - 1);
    float s = bdt[d];
    const float* dr = dbc + (size_t)l * NXP;
#pragma unroll
    for (int k = 0; k < DTR; k++) s += dr[k] * wdt[k * DI + d];
    dt[idx] = (s > 20.f) ? s : log1pf(__expf(s));
}

// ---------------- selective scan: phase 1 (per-chunk carries) ----------------
// thread t: d = bx*32 + (t>>4), s = t&15. chunk c = by.
__global__ __launch_bounds__(512)
void scan1_k(const float* __restrict__ dt, const float* __restrict__ u,
             const float* __restrict__ dbc, const float* __restrict__ Alog,
             float* __restrict__ cP, float* __restrict__ cS)
{
    const int t = threadIdx.x;
    const int dl = t >> 4, s = t & 15;
    const int d = blockIdx.x * 32 + dl;
    const int c = blockIdx.y;
    const float A = -__expf(Alog[d * DS + s]);
    const int l0 = c * CLEN;
    const float* pdt = dt  + (size_t)l0 * DI + d;
    const float* pu  = u   + (size_t)l0 * DI + d;
    const float* pB  = dbc + (size_t)l0 * NXP + DTR + s;
    float P = 1.f, S = 0.f;
#pragma unroll 4
    for (int i = 0; i < CLEN; i++) {
        const float dtv = pdt[i * DI];
        const float uv  = pu [i * DI];
        const float Bv  = pB [i * NXP];
        const float a = __expf(A * dtv);
        const float b = dtv * Bv * uv;
        P *= a;
        S = a * S + b;
    }
    const int idx = d * DS + s;
    cP[(size_t)c * (DI * DS) + idx] = P;
    cS[(size_t)c * (DI * DS) + idx] = S;
}

// ---------------- phase 2: sequential scan of chunk carries ----------------
__global__ __launch_bounds__(512)
void scan2_k(const float* __restrict__ cP, const float* __restrict__ cS,
             float* __restrict__ hin)
{
    const int idx = blockIdx.x * 512 + threadIdx.x;   // 0..8191
    float h = 0.f;
#pragma unroll 4
    for (int c = 0; c < NC; c++) {
        hin[(size_t)c * (DI * DS) + idx] = h;
        h = cP[(size_t)c * (DI * DS) + idx] * h + cS[(size_t)c * (DI * DS) + idx];
    }
}

// ---------------- phase 3: full scan + y reduction + skip + gating ----------------
__global__ __launch_bounds__(512)
void scan3_k(const float* __restrict__ dt, const float* __restrict__ u,
             const float* __restrict__ dbc, const float* __restrict__ Alog,
             const float* __restrict__ hin, const float* __restrict__ xz,
             const float* __restrict__ Dskip, float* __restrict__ yg)
{
    const int t = threadIdx.x;
    const int dl = t >> 4, s = t & 15;
    const int d = blockIdx.x * 32 + dl;
    const int c = blockIdx.y;
    const float A = -__expf(Alog[d * DS + s]);
    const float Dv = Dskip[d];
    const int l0 = c * CLEN;
    const float* pdt = dt  + (size_t)l0 * DI + d;
    const float* pu  = u   + (size_t)l0 * DI + d;
    const float* pB  = dbc + (size_t)l0 * NXP + DTR + s;
    const float* pC  = dbc + (size_t)l0 * NXP + DTR + DS + s;
    float h = hin[(size_t)c * (DI * DS) + d * DS + s];
#pragma unroll 2
    for (int i = 0; i < CLEN; i++) {
        const float dtv = pdt[i * DI];
        const float uv  = pu [i * DI];
        const float Bv  = pB [i * NXP];
        const float Cv  = pC [i * NXP];
        const float a = __expf(A * dtv);
        const float b = dtv * Bv * uv;
        h = a * h + b;
        float p = h * Cv;
        p += __shfl_xor_sync(0xffffffffu, p, 8);
        p += __shfl_xor_sync(0xffffffffu, p, 4);
        p += __shfl_xor_sync(0xffffffffu, p, 2);
        p += __shfl_xor_sync(0xffffffffu, p, 1);
        if (s == 0) {
            const int l = l0 + i;
            const float zv  = xz[(size_t)l * (2 * DI) + DI + d];
            const float sig = 1.f / (1.f + __expf(-zv));
            yg[(size_t)l * DI + d] = (p + uv * Dv) * (zv * sig);
        }
    }
}

// ---------------- host launch ----------------
static float* symaddr(const void* sym)
{
    void* p = nullptr;
    cudaGetSymbolAddress(&p, sym);
    return (float*)p;
}

extern "C" void kernel_launch(void* const* d_in, const int* in_sizes, int n_in,
                              void* d_out, int out_size)
{
    const float* x     = (const float*)d_in[0];
    const float* adj   = (const float*)d_in[1];
    const float* gcn_w = (const float*)d_in[2];
    const float* gcn_b = (const float*)d_in[3];
    const float* ln_g  = (const float*)d_in[4];
    const float* ln_b  = (const float*)d_in[5];
    const float* w_in  = (const float*)d_in[6];
    const float* conv_w= (const float*)d_in[7];
    const float* conv_b= (const float*)d_in[8];
    const float* w_xp  = (const float*)d_in[9];
    const float* w_dt  = (const float*)d_in[10];
    const float* b_dt  = (const float*)d_in[11];
    const float* A_log = (const float*)d_in[12];
    const float* D_skip= (const float*)d_in[13];
    const float* w_out = (const float*)d_in[14];
    float* out = (float*)d_out;

    float* t0  = symaddr(g_t0);
    float* h1  = symaddr(g_h1);
    float* hln = symaddr(g_hln);
    float* xz  = symaddr(g_xz);
    float* u   = symaddr(g_u);
    float* dbc = symaddr(g_dbc);
    float* dt  = symaddr(g_dt);
    float* cP  = symaddr(g_cP);
    float* cS  = symaddr(g_cS);
    float* hin = symaddr(g_hin);
    float* yg  = symaddr(g_yg);

    // 1) t0 = adj @ x                          [4096x4096 @ 4096x256]
    sgemm_k<false><<<dim3(DM / 64, LSEQ / 128), 256>>>(adj, x, nullptr, t0, LSEQ, DM, LSEQ);
    // 2) h1 = relu(t0 @ gcn_w + gcn_b)         [4096x256 @ 256x256]
    sgemm_k<true ><<<dim3(DM / 64, LSEQ / 128), 256>>>(t0, gcn_w, gcn_b, h1, LSEQ, DM, DM);
    // 3) layernorm
    ln_k<<<LSEQ, 256>>>(h1, ln_g, ln_b, hln);
    // 4) xz = hln @ w_in                       [4096x256 @ 256x1024]
    sgemm_k<false><<<dim3((2 * DI) / 64, LSEQ / 128), 256>>>(hln, w_in, nullptr, xz, LSEQ, 2 * DI, DM);
    // 5) u = silu(conv(xc) + b)
    conv_silu_k<<<(LSEQ * DI) / 256, 256>>>(xz, conv_w, conv_b, u);
    // 6) dbc = u @ w_xp                        [4096x512 @ 512x48]
    dbc_k<<<LSEQ / 8, 384>>>(u, w_xp, dbc);
    // 7) dt = softplus(dbc[:, :16] @ w_dt + b_dt)
    dt_k<<<(LSEQ * DI) / 256, 256>>>(dbc, w_dt, b_dt, dt);
    // 8-10) chunked selective scan (+ skip + gating fused)
    scan1_k<<<dim3(DI / 32, NC), 512>>>(dt, u, dbc, A_log, cP, cS);
    scan2_k<<<(DI * DS) / 512, 512>>>(cP, cS, hin);
    scan3_k<<<dim3(DI / 32, NC), 512>>>(dt, u, dbc, A_log, hin, xz, D_skip, yg);
    // 11) out = yg @ w_out                     [4096x512 @ 512x256]
    sgemm_k<false><<<dim3(DM / 64, LSEQ / 128), 256>>>(yg, w_out, nullptr, out, LSEQ, DM, DI);
}

// round 3
// speedup vs baseline: 1.6649x; 1.6649x over previous
#include <cuda_runtime.h>
#include <cstdint>
#include <math.h>

// ---------------- problem constants ----------------
#define LSEQ   4096
#define DM     256
#define DI     512          // D_INNER
#define DS     16           // D_STATE
#define DTR    16           // DT_RANK
#define NXP    48           // DT_RANK + 2*D_STATE
#define DCONV  4
#define NC     64           // scan chunks
#define CLEN   64           // steps per chunk
#define LN_EPS 1e-5f

// ---------------- device scratch ----------------
__device__ float g_t0  [LSEQ*DM];
__device__ float g_h1  [LSEQ*DM];
__device__ float g_hln [LSEQ*DM];
__device__ float g_xz  [LSEQ*2*DI];
__device__ float g_u   [LSEQ*DI];
__device__ float g_dbc [LSEQ*NXP];
__device__ float g_dt  [LSEQ*DI];
__device__ float g_cP  [NC*DI*DS];
__device__ float g_cS  [NC*DI*DS];
__device__ float g_hin [NC*DI*DS];
__device__ float g_yg  [LSEQ*DI];

// ================= helpers =================
__device__ __forceinline__ uint32_t smem_u32(const void* p) {
    uint32_t a;
    asm("{ .reg .u64 t; cvta.to.shared.u64 t, %1; cvt.u32.u64 %0, t; }" : "=r"(a) : "l"(p));
    return a;
}

#define CP_ASYNC16(dst, src) \
    asm volatile("cp.async.cg.shared.global [%0], [%1], 16;" :: "r"(dst), "l"(src))
#define CP_COMMIT() asm volatile("cp.async.commit_group;" ::: "memory")
#define CP_WAIT1()  asm volatile("cp.async.wait_group 1;"  ::: "memory")

#define LDMATRIX_X4(r, addr) \
    asm volatile("ldmatrix.sync.aligned.m8n8.x4.shared.b16 {%0,%1,%2,%3}, [%4];" \
        : "=r"((r)[0]), "=r"((r)[1]), "=r"((r)[2]), "=r"((r)[3]) : "r"(addr))

#define MMA_TF32(c, a, b) \
    asm volatile("mma.sync.aligned.m16n8k8.row.col.f32.tf32.tf32.f32 " \
        "{%0,%1,%2,%3},{%4,%5,%6,%7},{%8,%9},{%0,%1,%2,%3};" \
        : "+f"((c)[0]), "+f"((c)[1]), "+f"((c)[2]), "+f"((c)[3]) \
        : "r"((a)[0]), "r"((a)[1]), "r"((a)[2]), "r"((a)[3]), "r"((b)[0]), "r"((b)[1]))

// ================= mma.sync TF32-split GEMM =================
// C[M x Ng] = A[M x K] @ B[K x Ng]; block 128x64, BK=32, 8 warps (2M x 4N),
// warp tile 64x16, fp32-accurate via 3-term tf32 split (split in registers).
#define BM 128
#define BN 64
#define BK 32
#define A_STRIDE 36                      // floats per A smem row (pad for LDSM)
#define B_STRIDE 68                      // floats per B smem row
#define A_STAGE_F (BM * A_STRIDE)        // 4608 floats
#define B_STAGE_F (BK * B_STRIDE)        // 2176 floats
#define STAGE_F   (A_STAGE_F + B_STAGE_F)   // 6784 floats (27136 B, 16B-mult)
#define MMA_SMEM  (2 * STAGE_F * 4)

#define TF32_MASK 0xFFFFE000u

template<bool BIAS_RELU>
__global__ __launch_bounds__(256)
void mma_gemm(const float* __restrict__ A, const float* __restrict__ B,
              const float* __restrict__ bias, float* __restrict__ C,
              int K, int Ng)
{
    extern __shared__ float smem[];
    const uint32_t sb  = smem_u32(smem);
    const int tid  = threadIdx.x;
    const int wid  = tid >> 5, lane = tid & 31;
    const int warpM = wid & 1;            // 0..1
    const int warpN = wid >> 1;           // 0..3
    const int m0 = blockIdx.y * BM;
    const int n0 = blockIdx.x * BN;
    const int g  = lane >> 2;             // groupID 0..7
    const int tg = lane & 3;              // thread-in-group 0..3

    const int nch = K / BK;

    // ---- prefetch chunk c into stage s ----
    auto prefetch = [&](int c, int s) {
        const int k0 = c * BK;
        const uint32_t abase = sb + (uint32_t)s * STAGE_F * 4;
#pragma unroll
        for (int i = 0; i < 4; i++) {
            const int q = tid + i * 256;          // 0..1023
            const int row = q >> 3, seg = q & 7;
            CP_ASYNC16(abase + (uint32_t)(row * A_STRIDE + seg * 4) * 4,
                       A + (size_t)(m0 + row) * K + k0 + seg * 4);
        }
        const uint32_t bbase = abase + A_STAGE_F * 4;
#pragma unroll
        for (int i = 0; i < 2; i++) {
            const int q = tid + i * 256;          // 0..511
            const int kr = q >> 4, seg = q & 15;
            CP_ASYNC16(bbase + (uint32_t)(kr * B_STRIDE + seg * 4) * 4,
                       B + (size_t)(k0 + kr) * Ng + n0 + seg * 4);
        }
        CP_COMMIT();
    };

    float c[4][2][4];
#pragma unroll
    for (int mt = 0; mt < 4; mt++)
#pragma unroll
        for (int nt = 0; nt < 2; nt++)
#pragma unroll
            for (int i = 0; i < 4; i++) c[mt][nt][i] = 0.f;

    prefetch(0, 0);
    prefetch(1, 1);

    // per-lane ldmatrix address pieces (A)
    const int lrow  = (lane & 7) + ((lane >> 3) & 1) * 8;  // tile row
    const int lkoff = (lane >> 4) * 4;                     // tile col (floats)

    for (int ch = 0; ch < nch; ch++) {
        CP_WAIT1();
        __syncthreads();

        const int st = ch & 1;
        const uint32_t as = sb + (uint32_t)st * STAGE_F * 4;
        const float*   bp = smem + (size_t)st * STAGE_F + A_STAGE_F;
        const uint32_t a_lm = as + (uint32_t)((warpM * 64 + lrow) * A_STRIDE + lkoff) * 4;

#pragma unroll
        for (int kb = 0; kb < 4; kb++) {
            // ---- A fragments (raw) via ldmatrix ----
            uint32_t araw[4][4];
#pragma unroll
            for (int mt = 0; mt < 4; mt++)
                LDMATRIX_X4(araw[mt], a_lm + (uint32_t)(mt * 16 * A_STRIDE + kb * 8) * 4);

            // ---- B fragments (raw) via scalar LDS ----
            float braw[2][2];
#pragma unroll
            for (int nt = 0; nt < 2; nt++) {
                const int n = warpN * 16 + nt * 8 + g;
                const int k = kb * 8 + tg;
                braw[nt][0] = bp[k * B_STRIDE + n];
                braw[nt][1] = bp[(k + 4) * B_STRIDE + n];
            }

            // ---- register split: hi = trunc19(v), lo = v - hi ----
            uint32_t ahi[4][4], alo[4][4];
#pragma unroll
            for (int mt = 0; mt < 4; mt++)
#pragma unroll
                for (int i = 0; i < 4; i++) {
                    const uint32_t r = araw[mt][i];
                    const uint32_t h = r & TF32_MASK;
                    ahi[mt][i] = h;
                    alo[mt][i] = __float_as_uint(__uint_as_float(r) - __uint_as_float(h));
                }
            uint32_t bhi[2][2], blo[2][2];
#pragma unroll
            for (int nt = 0; nt < 2; nt++)
#pragma unroll
                for (int i = 0; i < 2; i++) {
                    const uint32_t r = __float_as_uint(braw[nt][i]);
                    const uint32_t h = r & TF32_MASK;
                    bhi[nt][i] = h;
                    blo[nt][i] = __float_as_uint(braw[nt][i] - __uint_as_float(h));
                }

            // ---- 3-term mma ----
#pragma unroll
            for (int mt = 0; mt < 4; mt++)
#pragma unroll
                for (int nt = 0; nt < 2; nt++) {
                    MMA_TF32(c[mt][nt], ahi[mt], blo[nt]);
                    MMA_TF32(c[mt][nt], alo[mt], bhi[nt]);
                    MMA_TF32(c[mt][nt], ahi[mt], bhi[nt]);
                }
        }
        __syncthreads();
        if (ch + 2 < nch) prefetch(ch + 2, st);
    }

    // ---- epilogue: direct float2 stores ----
#pragma unroll
    for (int mt = 0; mt < 4; mt++)
#pragma unroll
        for (int nt = 0; nt < 2; nt++) {
            const int row = m0 + warpM * 64 + mt * 16 + g;
            const int col = n0 + warpN * 16 + nt * 8 + 2 * tg;
            float2 v0 = make_float2(c[mt][nt][0], c[mt][nt][1]);
            float2 v1 = make_float2(c[mt][nt][2], c[mt][nt][3]);
            if (BIAS_RELU) {
                const float b0 = bias[col], b1 = bias[col + 1];
                v0.x = fmaxf(v0.x + b0, 0.f); v0.y = fmaxf(v0.y + b1, 0.f);
                v1.x = fmaxf(v1.x + b0, 0.f); v1.y = fmaxf(v1.y + b1, 0.f);
            }
            *(float2*)(C + (size_t)row * Ng + col)       = v0;
            *(float2*)(C + (size_t)(row + 8) * Ng + col) = v1;
        }
}

// ---------------- layernorm ----------------
__global__ __launch_bounds__(256)
void ln_k(const float* __restrict__ h1, const float* __restrict__ g,
          const float* __restrict__ b, float* __restrict__ out)
{
    const int row = blockIdx.x;
    const int tid = threadIdx.x;
    float v = h1[(size_t)row * DM + tid];
    float s = v, s2 = v * v;
#pragma unroll
    for (int o = 16; o; o >>= 1) {
        s  += __shfl_xor_sync(0xffffffffu, s,  o);
        s2 += __shfl_xor_sync(0xffffffffu, s2, o);
    }
    __shared__ float ws[8], ws2[8];
    if ((tid & 31) == 0) { ws[tid >> 5] = s; ws2[tid >> 5] = s2; }
    __syncthreads();
    float ts = 0.f, ts2 = 0.f;
#pragma unroll
    for (int i = 0; i < 8; i++) { ts += ws[i]; ts2 += ws2[i]; }
    const float mu  = ts * (1.f / DM);
    const float var = ts2 * (1.f / DM) - mu * mu;
    const float r   = rsqrtf(var + LN_EPS);
    out[(size_t)row * DM + tid] = (v - mu) * r * g[tid] + b[tid];
}

// ---------------- conv + silu ----------------
__global__ __launch_bounds__(256)
void conv_silu_k(const float* __restrict__ xz, const float* __restrict__ cw,
                 const float* __restrict__ cb, float* __restrict__ u)
{
    const int idx = blockIdx.x * 256 + threadIdx.x;
    const int l = idx >> 9, d = idx & (DI - 1);
    float s = cb[d];
#pragma unroll
    for (int k = 0; k < DCONV; k++) {
        const int ls = l - (DCONV - 1) + k;
        if (ls >= 0) s += xz[(size_t)ls * (2 * DI) + d] * cw[d * DCONV + k];
    }
    const float sig = 1.f / (1.f + __expf(-s));
    u[idx] = s * sig;
}

// ---------------- dbc = u @ w_xp ----------------
__global__ __launch_bounds__(384)
void dbc_k(const float* __restrict__ u, const float* __restrict__ wxp,
           float* __restrict__ dbc)
{
    __shared__ float us[8][DI + 1];
    const int tid = threadIdx.x;
    const int l0 = blockIdx.x * 8;
    for (int i = tid; i < 8 * DI; i += 384)
        us[i >> 9][i & (DI - 1)] = u[(size_t)l0 * DI + i];
    __syncthreads();
    const int j = tid % NXP, r = tid / NXP;
    const float* ur = us[r];
    float acc = 0.f;
#pragma unroll 8
    for (int k = 0; k < DI; k++) acc += ur[k] * wxp[k * NXP + j];
    dbc[(size_t)(l0 + r) * NXP + j] = acc;
}

// ---------------- dt ----------------
__global__ __launch_bounds__(256)
void dt_k(const float* __restrict__ dbc, const float* __restrict__ wdt,
          const float* __restrict__ bdt, float* __restrict__ dt)
{
    const int idx = blockIdx.x * 256 + threadIdx.x;
    const int l = idx >> 9, d = idx & (DI - 1);
    float s = bdt[d];
    const float* dr = dbc + (size_t)l * NXP;
#pragma unroll
    for (int k = 0; k < DTR; k++) s += dr[k] * wdt[k * DI + d];
    dt[idx] = (s > 20.f) ? s : log1pf(__expf(s));
}

// ---------------- scan phase 1 ----------------
__global__ __launch_bounds__(512)
void scan1_k(const float* __restrict__ dt, const float* __restrict__ u,
             const float* __restrict__ dbc, const float* __restrict__ Alog,
             float* __restrict__ cP, float* __restrict__ cS)
{
    const int t = threadIdx.x;
    const int dl = t >> 4, s = t & 15;
    const int d = blockIdx.x * 32 + dl;
    const int c = blockIdx.y;
    const float A = -__expf(Alog[d * DS + s]);
    const int l0 = c * CLEN;
    const float* pdt = dt  + (size_t)l0 * DI + d;
    const float* pu  = u   + (size_t)l0 * DI + d;
    const float* pB  = dbc + (size_t)l0 * NXP + DTR + s;
    float P = 1.f, S = 0.f;
#pragma unroll 4
    for (int i = 0; i < CLEN; i++) {
        const float dtv = pdt[i * DI];
        const float uv  = pu [i * DI];
        const float Bv  = pB [i * NXP];
        const float a = __expf(A * dtv);
        const float b = dtv * Bv * uv;
        P *= a;
        S = a * S + b;
    }
    const int idx = d * DS + s;
    cP[(size_t)c * (DI * DS) + idx] = P;
    cS[(size_t)c * (DI * DS) + idx] = S;
}

// ---------------- scan phase 2 ----------------
__global__ __launch_bounds__(512)
void scan2_k(const float* __restrict__ cP, const float* __restrict__ cS,
             float* __restrict__ hin)
{
    const int idx = blockIdx.x * 512 + threadIdx.x;
    float h = 0.f;
#pragma unroll 4
    for (int c = 0; c < NC; c++) {
        hin[(size_t)c * (DI * DS) + idx] = h;
        h = cP[(size_t)c * (DI * DS) + idx] * h + cS[(size_t)c * (DI * DS) + idx];
    }
}

// ---------------- scan phase 3 ----------------
__global__ __launch_bounds__(512)
void scan3_k(const float* __restrict__ dt, const float* __restrict__ u,
             const float* __restrict__ dbc, const float* __restrict__ Alog,
             const float* __restrict__ hin, const float* __restrict__ xz,
             const float* __restrict__ Dskip, float* __restrict__ yg)
{
    const int t = threadIdx.x;
    const int dl = t >> 4, s = t & 15;
    const int d = blockIdx.x * 32 + dl;
    const int c = blockIdx.y;
    const float A = -__expf(Alog[d * DS + s]);
    const float Dv = Dskip[d];
    const int l0 = c * CLEN;
    const float* pdt = dt  + (size_t)l0 * DI + d;
    const float* pu  = u   + (size_t)l0 * DI + d;
    const float* pB  = dbc + (size_t)l0 * NXP + DTR + s;
    const float* pC  = dbc + (size_t)l0 * NXP + DTR + DS + s;
    float h = hin[(size_t)c * (DI * DS) + d * DS + s];
#pragma unroll 2
    for (int i = 0; i < CLEN; i++) {
        const float dtv = pdt[i * DI];
        const float uv  = pu [i * DI];
        const float Bv  = pB [i * NXP];
        const float Cv  = pC [i * NXP];
        const float a = __expf(A * dtv);
        const float b = dtv * Bv * uv;
        h = a * h + b;
        float p = h * Cv;
        p += __shfl_xor_sync(0xffffffffu, p, 8);
        p += __shfl_xor_sync(0xffffffffu, p, 4);
        p += __shfl_xor_sync(0xffffffffu, p, 2);
        p += __shfl_xor_sync(0xffffffffu, p, 1);
        if (s == 0) {
            const int l = l0 + i;
            const float zv  = xz[(size_t)l * (2 * DI) + DI + d];
            const float sig = 1.f / (1.f + __expf(-zv));
            yg[(size_t)l * DI + d] = (p + uv * Dv) * (zv * sig);
        }
    }
}

// ---------------- host launch ----------------
static float* symaddr(const void* sym)
{
    void* p = nullptr;
    cudaGetSymbolAddress(&p, sym);
    return (float*)p;
}

extern "C" void kernel_launch(void* const* d_in, const int* in_sizes, int n_in,
                              void* d_out, int out_size)
{
    const float* x     = (const float*)d_in[0];
    const float* adj   = (const float*)d_in[1];
    const float* gcn_w = (const float*)d_in[2];
    const float* gcn_b = (const float*)d_in[3];
    const float* ln_g  = (const float*)d_in[4];
    const float* ln_b  = (const float*)d_in[5];
    const float* w_in  = (const float*)d_in[6];
    const float* conv_w= (const float*)d_in[7];
    const float* conv_b= (const float*)d_in[8];
    const float* w_xp  = (const float*)d_in[9];
    const float* w_dt  = (const float*)d_in[10];
    const float* b_dt  = (const float*)d_in[11];
    const float* A_log = (const float*)d_in[12];
    const float* D_skip= (const float*)d_in[13];
    const float* w_out = (const float*)d_in[14];
    float* out = (float*)d_out;

    float* t0  = symaddr(g_t0);
    float* h1  = symaddr(g_h1);
    float* hln = symaddr(g_hln);
    float* xz  = symaddr(g_xz);
    float* u   = symaddr(g_u);
    float* dbc = symaddr(g_dbc);
    float* dt  = symaddr(g_dt);
    float* cP  = symaddr(g_cP);
    float* cS  = symaddr(g_cS);
    float* hin = symaddr(g_hin);
    float* yg  = symaddr(g_yg);

    cudaFuncSetAttribute(mma_gemm<false>, cudaFuncAttributeMaxDynamicSharedMemorySize, MMA_SMEM);
    cudaFuncSetAttribute(mma_gemm<true >, cudaFuncAttributeMaxDynamicSharedMemorySize, MMA_SMEM);

    // 1) t0 = adj @ x                          [4096x4096 @ 4096x256]
    mma_gemm<false><<<dim3(DM / BN, LSEQ / BM), 256, MMA_SMEM>>>(adj, x, nullptr, t0, LSEQ, DM);
    // 2) h1 = relu(t0 @ gcn_w + gcn_b)         [4096x256 @ 256x256]
    mma_gemm<true ><<<dim3(DM / BN, LSEQ / BM), 256, MMA_SMEM>>>(t0, gcn_w, gcn_b, h1, DM, DM);
    // 3) layernorm
    ln_k<<<LSEQ, 256>>>(h1, ln_g, ln_b, hln);
    // 4) xz = hln @ w_in                       [4096x256 @ 256x1024]
    mma_gemm<false><<<dim3((2 * DI) / BN, LSEQ / BM), 256, MMA_SMEM>>>(hln, w_in, nullptr, xz, DM, 2 * DI);
    // 5) u = silu(conv(xc) + b)
    conv_silu_k<<<(LSEQ * DI) / 256, 256>>>(xz, conv_w, conv_b, u);
    // 6) dbc = u @ w_xp
    dbc_k<<<LSEQ / 8, 384>>>(u, w_xp, dbc);
    // 7) dt
    dt_k<<<(LSEQ * DI) / 256, 256>>>(dbc, w_dt, b_dt, dt);
    // 8-10) chunked selective scan
    scan1_k<<<dim3(DI / 32, NC), 512>>>(dt, u, dbc, A_log, cP, cS);
    scan2_k<<<(DI * DS) / 512, 512>>>(cP, cS, hin);
    scan3_k<<<dim3(DI / 32, NC), 512>>>(dt, u, dbc, A_log, hin, xz, D_skip, yg);
    // 11) out = yg @ w_out                     [4096x512 @ 512x256]
    mma_gemm<false><<<dim3(DM / BN, LSEQ / BM), 256, MMA_SMEM>>>(yg, w_out, nullptr, out, DI, DM);
}

// round 4
// speedup vs baseline: 1.7120x; 1.0283x over previous
#include <cuda_runtime.h>
#include <cstdint>
#include <math.h>

// ---------------- problem constants ----------------
#define LSEQ   4096
#define DM     256
#define DI     512          // D_INNER
#define DS     16           // D_STATE
#define DTR    16           // DT_RANK
#define NXP    48           // DT_RANK + 2*D_STATE (logical)
#define NXPAD  64           // padded dbc row stride
#define DCONV  4
#define NC     64           // scan chunks
#define CLEN   64           // steps per chunk
#define LN_EPS 1e-5f
#define KSPLIT 4            // split-K factor for adj@x

// ---------------- device scratch ----------------
__device__ float g_t0  [LSEQ*DM];
__device__ float g_part[KSPLIT*LSEQ*DM];   // split-K partials
__device__ float g_h1  [LSEQ*DM];
__device__ float g_hln [LSEQ*DM];
__device__ float g_xz  [LSEQ*2*DI];
__device__ float g_u   [LSEQ*DI];
__device__ float g_wxpp[DI*NXPAD];         // padded w_xp
__device__ float g_dbc [LSEQ*NXPAD];       // padded dbc
__device__ float g_dt  [LSEQ*DI];
__device__ float g_cP  [NC*DI*DS];
__device__ float g_cS  [NC*DI*DS];
__device__ float g_hin [NC*DI*DS];
__device__ float g_yg  [LSEQ*DI];

// ================= helpers =================
__device__ __forceinline__ uint32_t smem_u32(const void* p) {
    uint32_t a;
    asm("{ .reg .u64 t; cvta.to.shared.u64 t, %1; cvt.u32.u64 %0, t; }" : "=r"(a) : "l"(p));
    return a;
}

#define CP_ASYNC16(dst, src) \
    asm volatile("cp.async.cg.shared.global [%0], [%1], 16;" :: "r"(dst), "l"(src))
#define CP_COMMIT() asm volatile("cp.async.commit_group;" ::: "memory")
#define CP_WAIT1()  asm volatile("cp.async.wait_group 1;"  ::: "memory")

#define LDMATRIX_X4(r, addr) \
    asm volatile("ldmatrix.sync.aligned.m8n8.x4.shared.b16 {%0,%1,%2,%3}, [%4];" \
        : "=r"((r)[0]), "=r"((r)[1]), "=r"((r)[2]), "=r"((r)[3]) : "r"(addr))

#define MMA_TF32(c, a, b) \
    asm volatile("mma.sync.aligned.m16n8k8.row.col.f32.tf32.tf32.f32 " \
        "{%0,%1,%2,%3},{%4,%5,%6,%7},{%8,%9},{%0,%1,%2,%3};" \
        : "+f"((c)[0]), "+f"((c)[1]), "+f"((c)[2]), "+f"((c)[3]) \
        : "r"((a)[0]), "r"((a)[1]), "r"((a)[2]), "r"((a)[3]), "r"((b)[0]), "r"((b)[1]))

// ================= mma.sync TF32-split GEMM =================
// Cz[M x Ng] = A[:, z*K : (z+1)*K] @ B[z*K : (z+1)*K, :]
// block 128x64, BK=32, 8 warps (2M x 4N), warp tile 64x16.
// fp32-accurate via 3-term tf32 split (done in registers).
#define BM 128
#define BN 64
#define BK 32
#define A_STRIDE 36
#define B_STRIDE 68
#define A_STAGE_F (BM * A_STRIDE)
#define B_STAGE_F (BK * B_STRIDE)
#define STAGE_F   (A_STAGE_F + B_STAGE_F)
#define MMA_SMEM  (2 * STAGE_F * 4)

#define TF32_MASK 0xFFFFE000u

template<bool BIAS_RELU>
__global__ __launch_bounds__(256, 4)
void mma_gemm(const float* __restrict__ A, const float* __restrict__ B,
              const float* __restrict__ bias, float* __restrict__ C,
              int K, int Ng, int lda, size_t csplit)
{
    extern __shared__ float smem[];
    const uint32_t sb  = smem_u32(smem);
    const int tid  = threadIdx.x;
    const int wid  = tid >> 5, lane = tid & 31;
    const int warpM = wid & 1;
    const int warpN = wid >> 1;
    const int m0 = blockIdx.y * BM;
    const int n0 = blockIdx.x * BN;
    const int z  = blockIdx.z;
    const int g  = lane >> 2;
    const int tg = lane & 3;

    const float* Az = A + (size_t)z * K;          // column offset into A
    const float* Bz = B + (size_t)z * K * Ng;     // row offset into B
    float*       Cz = C + (size_t)z * csplit;

    const int nch = K / BK;

    auto prefetch = [&](int c, int s) {
        const int k0 = c * BK;
        const uint32_t abase = sb + (uint32_t)s * STAGE_F * 4;
#pragma unroll
        for (int i = 0; i < 4; i++) {
            const int q = tid + i * 256;
            const int row = q >> 3, seg = q & 7;
            CP_ASYNC16(abase + (uint32_t)(row * A_STRIDE + seg * 4) * 4,
                       Az + (size_t)(m0 + row) * lda + k0 + seg * 4);
        }
        const uint32_t bbase = abase + A_STAGE_F * 4;
#pragma unroll
        for (int i = 0; i < 2; i++) {
            const int q = tid + i * 256;
            const int kr = q >> 4, seg = q & 15;
            CP_ASYNC16(bbase + (uint32_t)(kr * B_STRIDE + seg * 4) * 4,
                       Bz + (size_t)(k0 + kr) * Ng + n0 + seg * 4);
        }
        CP_COMMIT();
    };

    float c[4][2][4];
#pragma unroll
    for (int mt = 0; mt < 4; mt++)
#pragma unroll
        for (int nt = 0; nt < 2; nt++)
#pragma unroll
            for (int i = 0; i < 4; i++) c[mt][nt][i] = 0.f;

    prefetch(0, 0);
    prefetch(1, 1);

    const int lrow  = (lane & 7) + ((lane >> 3) & 1) * 8;
    const int lkoff = (lane >> 4) * 4;

    for (int ch = 0; ch < nch; ch++) {
        CP_WAIT1();
        __syncthreads();

        const int st = ch & 1;
        const uint32_t as = sb + (uint32_t)st * STAGE_F * 4;
        const float*   bp = smem + (size_t)st * STAGE_F + A_STAGE_F;
        const uint32_t a_lm = as + (uint32_t)((warpM * 64 + lrow) * A_STRIDE + lkoff) * 4;

#pragma unroll
        for (int kb = 0; kb < 4; kb++) {
            uint32_t araw[4][4];
#pragma unroll
            for (int mt = 0; mt < 4; mt++)
                LDMATRIX_X4(araw[mt], a_lm + (uint32_t)(mt * 16 * A_STRIDE + kb * 8) * 4);

            float braw[2][2];
#pragma unroll
            for (int nt = 0; nt < 2; nt++) {
                const int n = warpN * 16 + nt * 8 + g;
                const int k = kb * 8 + tg;
                braw[nt][0] = bp[k * B_STRIDE + n];
                braw[nt][1] = bp[(k + 4) * B_STRIDE + n];
            }

            uint32_t ahi[4][4], alo[4][4];
#pragma unroll
            for (int mt = 0; mt < 4; mt++)
#pragma unroll
                for (int i = 0; i < 4; i++) {
                    const uint32_t r = araw[mt][i];
                    const uint32_t h = r & TF32_MASK;
                    ahi[mt][i] = h;
                    alo[mt][i] = __float_as_uint(__uint_as_float(r) - __uint_as_float(h));
                }
            uint32_t bhi[2][2], blo[2][2];
#pragma unroll
            for (int nt = 0; nt < 2; nt++)
#pragma unroll
                for (int i = 0; i < 2; i++) {
                    const uint32_t r = __float_as_uint(braw[nt][i]);
                    const uint32_t h = r & TF32_MASK;
                    bhi[nt][i] = h;
                    blo[nt][i] = __float_as_uint(braw[nt][i] - __uint_as_float(h));
                }

#pragma unroll
            for (int mt = 0; mt < 4; mt++)
#pragma unroll
                for (int nt = 0; nt < 2; nt++) {
                    MMA_TF32(c[mt][nt], ahi[mt], blo[nt]);
                    MMA_TF32(c[mt][nt], alo[mt], bhi[nt]);
                    MMA_TF32(c[mt][nt], ahi[mt], bhi[nt]);
                }
        }
        __syncthreads();
        if (ch + 2 < nch) prefetch(ch + 2, st);
    }

#pragma unroll
    for (int mt = 0; mt < 4; mt++)
#pragma unroll
        for (int nt = 0; nt < 2; nt++) {
            const int row = m0 + warpM * 64 + mt * 16 + g;
            const int col = n0 + warpN * 16 + nt * 8 + 2 * tg;
            float2 v0 = make_float2(c[mt][nt][0], c[mt][nt][1]);
            float2 v1 = make_float2(c[mt][nt][2], c[mt][nt][3]);
            if (BIAS_RELU) {
                const float b0 = bias[col], b1 = bias[col + 1];
                v0.x = fmaxf(v0.x + b0, 0.f); v0.y = fmaxf(v0.y + b1, 0.f);
                v1.x = fmaxf(v1.x + b0, 0.f); v1.y = fmaxf(v1.y + b1, 0.f);
            }
            *(float2*)(Cz + (size_t)row * Ng + col)       = v0;
            *(float2*)(Cz + (size_t)(row + 8) * Ng + col) = v1;
        }
}

// ---------------- split-K reduction: t0 = sum of 4 partials ----------------
__global__ __launch_bounds__(256)
void reduce4_k(const float* __restrict__ p, float* __restrict__ out)
{
    const int i = (blockIdx.x * 256 + threadIdx.x) * 4;
    float4 a = *(const float4*)(p + i);
    float4 b = *(const float4*)(p + (size_t)LSEQ * DM + i);
    float4 cc= *(const float4*)(p + 2 * (size_t)LSEQ * DM + i);
    float4 d = *(const float4*)(p + 3 * (size_t)LSEQ * DM + i);
    float4 o;
    o.x = (a.x + b.x) + (cc.x + d.x);
    o.y = (a.y + b.y) + (cc.y + d.y);
    o.z = (a.z + b.z) + (cc.z + d.z);
    o.w = (a.w + b.w) + (cc.w + d.w);
    *(float4*)(out + i) = o;
}

// ---------------- pad w_xp 512x48 -> 512x64 (zero fill) ----------------
__global__ __launch_bounds__(256)
void padw_k(const float* __restrict__ wxp, float* __restrict__ wxpp)
{
    const int i = blockIdx.x * 256 + threadIdx.x;   // over DI*NXPAD
    const int r = i >> 6, col = i & 63;
    wxpp[i] = (col < NXP) ? wxp[r * NXP + col] : 0.f;
}

// ---------------- layernorm ----------------
__global__ __launch_bounds__(256)
void ln_k(const float* __restrict__ h1, const float* __restrict__ g,
          const float* __restrict__ b, float* __restrict__ out)
{
    const int row = blockIdx.x;
    const int tid = threadIdx.x;
    float v = h1[(size_t)row * DM + tid];
    float s = v, s2 = v * v;
#pragma unroll
    for (int o = 16; o; o >>= 1) {
        s  += __shfl_xor_sync(0xffffffffu, s,  o);
        s2 += __shfl_xor_sync(0xffffffffu, s2, o);
    }
    __shared__ float ws[8], ws2[8];
    if ((tid & 31) == 0) { ws[tid >> 5] = s; ws2[tid >> 5] = s2; }
    __syncthreads();
    float ts = 0.f, ts2 = 0.f;
#pragma unroll
    for (int i = 0; i < 8; i++) { ts += ws[i]; ts2 += ws2[i]; }
    const float mu  = ts * (1.f / DM);
    const float var = ts2 * (1.f / DM) - mu * mu;
    const float r   = rsqrtf(var + LN_EPS);
    out[(size_t)row * DM + tid] = (v - mu) * r * g[tid] + b[tid];
}

// ---------------- conv + silu ----------------
__global__ __launch_bounds__(256)
void conv_silu_k(const float* __restrict__ xz, const float* __restrict__ cw,
                 const float* __restrict__ cb, float* __restrict__ u)
{
    const int idx = blockIdx.x * 256 + threadIdx.x;
    const int l = idx >> 9, d = idx & (DI - 1);
    float s = cb[d];
#pragma unroll
    for (int k = 0; k < DCONV; k++) {
        const int ls = l - (DCONV - 1) + k;
        if (ls >= 0) s += xz[(size_t)ls * (2 * DI) + d] * cw[d * DCONV + k];
    }
    const float sig = 1.f / (1.f + __expf(-s));
    u[idx] = s * sig;
}

// ---------------- dt = softplus(dbc[:, :16] @ w_dt + b_dt) ----------------
__global__ __launch_bounds__(256)
void dt_k(const float* __restrict__ dbc, const float* __restrict__ wdt,
          const float* __restrict__ bdt, float* __restrict__ dt)
{
    const int idx = blockIdx.x * 256 + threadIdx.x;
    const int l = idx >> 9, d = idx & (DI - 1);
    float s = bdt[d];
    const float* dr = dbc + (size_t)l * NXPAD;
#pragma unroll
    for (int k = 0; k < DTR; k++) s += dr[k] * wdt[k * DI + d];
    dt[idx] = (s > 20.f) ? s : log1pf(__expf(s));
}

// ---------------- scan phase 1 ----------------
__global__ __launch_bounds__(512)
void scan1_k(const float* __restrict__ dt, const float* __restrict__ u,
             const float* __restrict__ dbc, const float* __restrict__ Alog,
             float* __restrict__ cP, float* __restrict__ cS)
{
    const int t = threadIdx.x;
    const int dl = t >> 4, s = t & 15;
    const int d = blockIdx.x * 32 + dl;
    const int c = blockIdx.y;
    const float A = -__expf(Alog[d * DS + s]);
    const int l0 = c * CLEN;
    const float* pdt = dt  + (size_t)l0 * DI + d;
    const float* pu  = u   + (size_t)l0 * DI + d;
    const float* pB  = dbc + (size_t)l0 * NXPAD + DTR + s;
    float P = 1.f, S = 0.f;
#pragma unroll 4
    for (int i = 0; i < CLEN; i++) {
        const float dtv = pdt[i * DI];
        const float uv  = pu [i * DI];
        const float Bv  = pB [i * NXPAD];
        const float a = __expf(A * dtv);
        const float b = dtv * Bv * uv;
        P *= a;
        S = a * S + b;
    }
    const int idx = d * DS + s;
    cP[(size_t)c * (DI * DS) + idx] = P;
    cS[(size_t)c * (DI * DS) + idx] = S;
}

// ---------------- scan phase 2 ----------------
__global__ __launch_bounds__(512)
void scan2_k(const float* __restrict__ cP, const float* __restrict__ cS,
             float* __restrict__ hin)
{
    const int idx = blockIdx.x * 512 + threadIdx.x;
    float h = 0.f;
#pragma unroll 4
    for (int c = 0; c < NC; c++) {
        hin[(size_t)c * (DI * DS) + idx] = h;
        h = cP[(size_t)c * (DI * DS) + idx] * h + cS[(size_t)c * (DI * DS) + idx];
    }
}

// ---------------- scan phase 3 ----------------
__global__ __launch_bounds__(512)
void scan3_k(const float* __restrict__ dt, const float* __restrict__ u,
             const float* __restrict__ dbc, const float* __restrict__ Alog,
             const float* __restrict__ hin, const float* __restrict__ xz,
             const float* __restrict__ Dskip, float* __restrict__ yg)
{
    const int t = threadIdx.x;
    const int dl = t >> 4, s = t & 15;
    const int d = blockIdx.x * 32 + dl;
    const int c = blockIdx.y;
    const float A = -__expf(Alog[d * DS + s]);
    const float Dv = Dskip[d];
    const int l0 = c * CLEN;
    const float* pdt = dt  + (size_t)l0 * DI + d;
    const float* pu  = u   + (size_t)l0 * DI + d;
    const float* pB  = dbc + (size_t)l0 * NXPAD + DTR + s;
    const float* pC  = dbc + (size_t)l0 * NXPAD + DTR + DS + s;
    float h = hin[(size_t)c * (DI * DS) + d * DS + s];
#pragma unroll 2
    for (int i = 0; i < CLEN; i++) {
        const float dtv = pdt[i * DI];
        const float uv  = pu [i * DI];
        const float Bv  = pB [i * NXPAD];
        const float Cv  = pC [i * NXPAD];
        const float a = __expf(A * dtv);
        const float b = dtv * Bv * uv;
        h = a * h + b;
        float p = h * Cv;
        p += __shfl_xor_sync(0xffffffffu, p, 8);
        p += __shfl_xor_sync(0xffffffffu, p, 4);
        p += __shfl_xor_sync(0xffffffffu, p, 2);
        p += __shfl_xor_sync(0xffffffffu, p, 1);
        if (s == 0) {
            const int l = l0 + i;
            const float zv  = xz[(size_t)l * (2 * DI) + DI + d];
            const float sig = 1.f / (1.f + __expf(-zv));
            yg[(size_t)l * DI + d] = (p + uv * Dv) * (zv * sig);
        }
    }
}

// ---------------- host launch ----------------
static float* symaddr(const void* sym)
{
    void* p = nullptr;
    cudaGetSymbolAddress(&p, sym);
    return (float*)p;
}

extern "C" void kernel_launch(void* const* d_in, const int* in_sizes, int n_in,
                              void* d_out, int out_size)
{
    const float* x     = (const float*)d_in[0];
    const float* adj   = (const float*)d_in[1];
    const float* gcn_w = (const float*)d_in[2];
    const float* gcn_b = (const float*)d_in[3];
    const float* ln_g  = (const float*)d_in[4];
    const float* ln_b  = (const float*)d_in[5];
    const float* w_in  = (const float*)d_in[6];
    const float* conv_w= (const float*)d_in[7];
    const float* conv_b= (const float*)d_in[8];
    const float* w_xp  = (const float*)d_in[9];
    const float* w_dt  = (const float*)d_in[10];
    const float* b_dt  = (const float*)d_in[11];
    const float* A_log = (const float*)d_in[12];
    const float* D_skip= (const float*)d_in[13];
    const float* w_out = (const float*)d_in[14];
    float* out = (float*)d_out;

    float* t0   = symaddr(g_t0);
    float* part = symaddr(g_part);
    float* h1   = symaddr(g_h1);
    float* hln  = symaddr(g_hln);
    float* xz   = symaddr(g_xz);
    float* u    = symaddr(g_u);
    float* wxpp = symaddr(g_wxpp);
    float* dbc  = symaddr(g_dbc);
    float* dt   = symaddr(g_dt);
    float* cP   = symaddr(g_cP);
    float* cS   = symaddr(g_cS);
    float* hin  = symaddr(g_hin);
    float* yg   = symaddr(g_yg);

    cudaFuncSetAttribute(mma_gemm<false>, cudaFuncAttributeMaxDynamicSharedMemorySize, MMA_SMEM);
    cudaFuncSetAttribute(mma_gemm<true >, cudaFuncAttributeMaxDynamicSharedMemorySize, MMA_SMEM);

    // 0) pad w_xp (cheap, every call for determinism)
    padw_k<<<(DI * NXPAD) / 256, 256>>>(w_xp, wxpp);

    // 1) part[z] = adj[:, zK:(z+1)K] @ x[zK:(z+1)K, :]   split-K=4
    mma_gemm<false><<<dim3(DM / BN, LSEQ / BM, KSPLIT), 256, MMA_SMEM>>>(
        adj, x, nullptr, part, LSEQ / KSPLIT, DM, LSEQ, (size_t)LSEQ * DM);
    reduce4_k<<<(LSEQ * DM) / 1024, 256>>>(part, t0);

    // 2) h1 = relu(t0 @ gcn_w + gcn_b)
    mma_gemm<true ><<<dim3(DM / BN, LSEQ / BM), 256, MMA_SMEM>>>(
        t0, gcn_w, gcn_b, h1, DM, DM, DM, 0);
    // 3) layernorm
    ln_k<<<LSEQ, 256>>>(h1, ln_g, ln_b, hln);
    // 4) xz = hln @ w_in
    mma_gemm<false><<<dim3((2 * DI) / BN, LSEQ / BM), 256, MMA_SMEM>>>(
        hln, w_in, nullptr, xz, DM, 2 * DI, DM, 0);
    // 5) u = silu(conv(xc) + b)
    conv_silu_k<<<(LSEQ * DI) / 256, 256>>>(xz, conv_w, conv_b, u);
    // 6) dbc = u @ w_xp (padded N=64)
    mma_gemm<false><<<dim3(NXPAD / BN, LSEQ / BM), 256, MMA_SMEM>>>(
        u, wxpp, nullptr, dbc, DI, NXPAD, DI, 0);
    // 7) dt
    dt_k<<<(LSEQ * DI) / 256, 256>>>(dbc, w_dt, b_dt, dt);
    // 8-10) chunked selective scan
    scan1_k<<<dim3(DI / 32, NC), 512>>>(dt, u, dbc, A_log, cP, cS);
    scan2_k<<<(DI * DS) / 512, 512>>>(cP, cS, hin);
    scan3_k<<<dim3(DI / 32, NC), 512>>>(dt, u, dbc, A_log, hin, xz, D_skip, yg);
    // 11) out = yg @ w_out
    mma_gemm<false><<<dim3(DM / BN, LSEQ / BM), 256, MMA_SMEM>>>(
        yg, w_out, nullptr, out, DI, DM, DI, 0);
}

// round 5
// speedup vs baseline: 2.2851x; 1.3348x over previous
#include <cuda_runtime.h>
#include <cuda_bf16.h>
#include <cstdint>
#include <math.h>

// ---------------- problem constants ----------------
#define LSEQ   4096
#define DM     256
#define DI     512
#define DS     16
#define DTR    16
#define NXP    48
#define NXPAD  64
#define DCONV  4
#define NC     64
#define CLEN   64
#define LN_EPS 1e-5f

// ---------------- device scratch ----------------
__device__ float g_t0  [LSEQ*DM];
__device__ float g_part[4*LSEQ*DM];        // split-K partials (max 4 x 1M)
__device__ float g_h1  [LSEQ*DM];
__device__ float g_hln [LSEQ*DM];
__device__ float g_xz  [LSEQ*2*DI];
__device__ float g_u   [LSEQ*DI];
__device__ float g_wxpp[DI*NXPAD];
__device__ float g_dbc [LSEQ*NXPAD];
__device__ float g_dt  [LSEQ*DI];
__device__ float g_cP  [NC*DI*DS];
__device__ float g_cS  [NC*DI*DS];
__device__ float g_hin [NC*DI*DS];
__device__ float g_yg  [LSEQ*DI];

// ================= helpers =================
__device__ __forceinline__ uint32_t smem_u32(const void* p) {
    uint32_t a;
    asm("{ .reg .u64 t; cvta.to.shared.u64 t, %1; cvt.u32.u64 %0, t; }" : "=r"(a) : "l"(p));
    return a;
}

#define LDMATRIX_X4(r, addr) \
    asm volatile("ldmatrix.sync.aligned.m8n8.x4.shared.b16 {%0,%1,%2,%3}, [%4];" \
        : "=r"((r)[0]), "=r"((r)[1]), "=r"((r)[2]), "=r"((r)[3]) : "r"(addr))

#define MMA_BF16(c, a, b) \
    asm volatile("mma.sync.aligned.m16n8k16.row.col.f32.bf16.bf16.f32 " \
        "{%0,%1,%2,%3},{%4,%5,%6,%7},{%8,%9},{%0,%1,%2,%3};" \
        : "+f"((c)[0]), "+f"((c)[1]), "+f"((c)[2]), "+f"((c)[3]) \
        : "r"((a)[0]), "r"((a)[1]), "r"((a)[2]), "r"((a)[3]), "r"((b)[0]), "r"((b)[1]))

__device__ __forceinline__ uint32_t pack2(float e0, float e1) {
    __nv_bfloat162 v = __floats2bfloat162_rn(e0, e1);   // .x = e0 (low 16)
    return *(uint32_t*)&v;
}
__device__ __forceinline__ void split1(float v, float& hi, float& lo) {
    __nv_bfloat16 h = __float2bfloat16_rn(v);
    hi = __bfloat162float(h);
    lo = v - hi;
}

// ================= bf16x3-split GEMM =================
// C[M x Ng] (+ split-K z) = A slice @ B slice. block 128x64, BK=32,
// 8 warps (2M x 4N), warp tile 64x16. fp32-class accuracy:
// C = Ahi*Bhi + Ahi*Blo + Alo*Bhi  (hi/lo bf16 split done once per CTA at stage time)
#define BM 128
#define BN 64
#define BK 32
#define ASTR   40        // b16 elements per A smem row (80B, 16B-mult, LDSM conflict-free)
#define BSTRW  72        // 32-bit words per B k2-row (conflict-free LDS)
#define A_HI_OFF 0
#define A_LO_OFF (BM*ASTR*2)                 // 10240
#define B_HI_OFF (2*BM*ASTR*2)               // 20480
#define B_LO_OFF (B_HI_OFF + 16*BSTRW*4)     // 25088
#define MMA_SMEM (B_LO_OFF + 16*BSTRW*4)     // 29696

template<bool BIAS_RELU>
__global__ __launch_bounds__(256)
void mma_gemm(const float* __restrict__ A, const float* __restrict__ B,
              const float* __restrict__ bias, float* __restrict__ C,
              int K, int Ng, int lda, size_t csplit)
{
    extern __shared__ char smem[];
    const uint32_t sb = smem_u32(smem);
    const int tid  = threadIdx.x;
    const int wid  = tid >> 5, lane = tid & 31;
    const int warpM = wid & 1, warpN = wid >> 1;
    const int m0 = blockIdx.y * BM;
    const int n0 = blockIdx.x * BN;
    const int z  = blockIdx.z;
    const int g  = lane >> 2, tg = lane & 3;

    const float* Az = A + (size_t)z * K;
    const float* Bz = B + (size_t)z * K * Ng;
    float*       Cz = C + (size_t)z * csplit;
    const int nch = K / BK;

    // staging indices
    const int arow0 = tid >> 3;          // + 32*i
    const int aseg  = tid & 7;           // k segment (4 floats)
    const int bk2   = tid >> 4;          // 0..15 (k-pair row)
    const int bn4   = (tid & 15) * 4;    // 4 n columns

    float4 ga[4], gb0, gb1;
    auto ldG = [&](int c) {
        const int k0 = c * BK;
#pragma unroll
        for (int i = 0; i < 4; i++)
            ga[i] = *(const float4*)(Az + (size_t)(m0 + arow0 + 32 * i) * lda + k0 + aseg * 4);
        gb0 = *(const float4*)(Bz + (size_t)(k0 + 2 * bk2)     * Ng + n0 + bn4);
        gb1 = *(const float4*)(Bz + (size_t)(k0 + 2 * bk2 + 1) * Ng + n0 + bn4);
    };

    auto stS = [&]() {
#pragma unroll
        for (int i = 0; i < 4; i++) {
            const float* e = &ga[i].x;
            float h[4], l[4];
#pragma unroll
            for (int j = 0; j < 4; j++) split1(e[j], h[j], l[j]);
            uint2 hv = make_uint2(pack2(h[0], h[1]), pack2(h[2], h[3]));
            uint2 lv = make_uint2(pack2(l[0], l[1]), pack2(l[2], l[3]));
            const uint32_t off = (uint32_t)((arow0 + 32 * i) * ASTR + aseg * 4) * 2;
            *(uint2*)(smem + A_HI_OFF + off) = hv;
            *(uint2*)(smem + A_LO_OFF + off) = lv;
        }
        const float* e0 = &gb0.x;
        const float* e1 = &gb1.x;
        uint32_t* bh = (uint32_t*)(smem + B_HI_OFF);
        uint32_t* bl = (uint32_t*)(smem + B_LO_OFF);
#pragma unroll
        for (int j = 0; j < 4; j++) {
            float h0, l0, h1, l1;
            split1(e0[j], h0, l0);
            split1(e1[j], h1, l1);
            bh[bk2 * BSTRW + bn4 + j] = pack2(h0, h1);   // {k even, k odd}
            bl[bk2 * BSTRW + bn4 + j] = pack2(l0, l1);
        }
    };

    float c[4][2][4];
#pragma unroll
    for (int mt = 0; mt < 4; mt++)
#pragma unroll
        for (int nt = 0; nt < 2; nt++)
#pragma unroll
            for (int i = 0; i < 4; i++) c[mt][nt][i] = 0.f;

    // lane-dependent LDSM base: row = warpM*64 + (lane&15), col = (lane>>4)*8
    const uint32_t aHiB = sb + A_HI_OFF +
        (uint32_t)((warpM * 64 + (lane & 15)) * ASTR + (lane >> 4) * 8) * 2;

    ldG(0);
    for (int ch = 0; ch < nch; ch++) {
        stS();
        __syncthreads();
        if (ch + 1 < nch) ldG(ch + 1);

        const uint32_t* bh = (const uint32_t*)(smem + B_HI_OFF);
        const uint32_t* bl = (const uint32_t*)(smem + B_LO_OFF);
#pragma unroll
        for (int kh = 0; kh < 2; kh++) {
            uint32_t bhi[2][2], blo[2][2];
#pragma unroll
            for (int nt = 0; nt < 2; nt++) {
                const int w = (kh * 8 + tg) * BSTRW + warpN * 16 + nt * 8 + g;
                bhi[nt][0] = bh[w];  bhi[nt][1] = bh[w + 4 * BSTRW];
                blo[nt][0] = bl[w];  blo[nt][1] = bl[w + 4 * BSTRW];
            }
#pragma unroll
            for (int mt = 0; mt < 4; mt++) {
                uint32_t ah[4], al[4];
                const uint32_t off = (uint32_t)(mt * 16 * ASTR + kh * 16) * 2;
                LDMATRIX_X4(ah, aHiB + off);
                LDMATRIX_X4(al, aHiB + A_LO_OFF + off);
#pragma unroll
                for (int nt = 0; nt < 2; nt++) {
                    MMA_BF16(c[mt][nt], ah, bhi[nt]);
                    MMA_BF16(c[mt][nt], ah, blo[nt]);
                    MMA_BF16(c[mt][nt], al, bhi[nt]);
                }
            }
        }
        __syncthreads();
    }

    // ---- epilogue ----
#pragma unroll
    for (int mt = 0; mt < 4; mt++)
#pragma unroll
        for (int nt = 0; nt < 2; nt++) {
            const int row = m0 + warpM * 64 + mt * 16 + g;
            const int col = n0 + warpN * 16 + nt * 8 + 2 * tg;
            float2 v0 = make_float2(c[mt][nt][0], c[mt][nt][1]);
            float2 v1 = make_float2(c[mt][nt][2], c[mt][nt][3]);
            if (BIAS_RELU) {
                const float b0 = bias[col], b1 = bias[col + 1];
                v0.x = fmaxf(v0.x + b0, 0.f); v0.y = fmaxf(v0.y + b1, 0.f);
                v1.x = fmaxf(v1.x + b0, 0.f); v1.y = fmaxf(v1.y + b1, 0.f);
            }
            *(float2*)(Cz + (size_t)row * Ng + col)       = v0;
            *(float2*)(Cz + (size_t)(row + 8) * Ng + col) = v1;
        }
}

// ---------------- split-K reduction (count partials of n floats) ----------------
__global__ __launch_bounds__(256)
void reduce_k(const float* __restrict__ p, float* __restrict__ out,
              size_t stride, int count)
{
    const size_t i = ((size_t)blockIdx.x * 256 + threadIdx.x) * 4;
    float4 s = *(const float4*)(p + i);
    for (int cc = 1; cc < count; cc++) {
        float4 v = *(const float4*)(p + cc * stride + i);
        s.x += v.x; s.y += v.y; s.z += v.z; s.w += v.w;
    }
    *(float4*)(out + i) = s;
}

// ---------------- pad w_xp 512x48 -> 512x64 ----------------
__global__ __launch_bounds__(256)
void padw_k(const float* __restrict__ wxp, float* __restrict__ wxpp)
{
    const int i = blockIdx.x * 256 + threadIdx.x;
    const int r = i >> 6, col = i & 63;
    wxpp[i] = (col < NXP) ? wxp[r * NXP + col] : 0.f;
}

// ---------------- layernorm ----------------
__global__ __launch_bounds__(256)
void ln_k(const float* __restrict__ h1, const float* __restrict__ g,
          const float* __restrict__ b, float* __restrict__ out)
{
    const int row = blockIdx.x;
    const int tid = threadIdx.x;
    float v = h1[(size_t)row * DM + tid];
    float s = v, s2 = v * v;
#pragma unroll
    for (int o = 16; o; o >>= 1) {
        s  += __shfl_xor_sync(0xffffffffu, s,  o);
        s2 += __shfl_xor_sync(0xffffffffu, s2, o);
    }
    __shared__ float ws[8], ws2[8];
    if ((tid & 31) == 0) { ws[tid >> 5] = s; ws2[tid >> 5] = s2; }
    __syncthreads();
    float ts = 0.f, ts2 = 0.f;
#pragma unroll
    for (int i = 0; i < 8; i++) { ts += ws[i]; ts2 += ws2[i]; }
    const float mu  = ts * (1.f / DM);
    const float var = ts2 * (1.f / DM) - mu * mu;
    const float r   = rsqrtf(var + LN_EPS);
    out[(size_t)row * DM + tid] = (v - mu) * r * g[tid] + b[tid];
}

// ---------------- conv + silu ----------------
__global__ __launch_bounds__(256)
void conv_silu_k(const float* __restrict__ xz, const float* __restrict__ cw,
                 const float* __restrict__ cb, float* __restrict__ u)
{
    const int idx = blockIdx.x * 256 + threadIdx.x;
    const int l = idx >> 9, d = idx & (DI - 1);
    float s = cb[d];
#pragma unroll
    for (int k = 0; k < DCONV; k++) {
        const int ls = l - (DCONV - 1) + k;
        if (ls >= 0) s += xz[(size_t)ls * (2 * DI) + d] * cw[d * DCONV + k];
    }
    const float sig = 1.f / (1.f + __expf(-s));
    u[idx] = s * sig;
}

// ---------------- dt ----------------
__global__ __launch_bounds__(256)
void dt_k(const float* __restrict__ dbc, const float* __restrict__ wdt,
          const float* __restrict__ bdt, float* __restrict__ dt)
{
    const int idx = blockIdx.x * 256 + threadIdx.x;
    const int l = idx >> 9, d = idx & (DI - 1);
    float s = bdt[d];
    const float* dr = dbc + (size_t)l * NXPAD;
#pragma unroll
    for (int k = 0; k < DTR; k++) s += dr[k] * wdt[k * DI + d];
    dt[idx] = (s > 20.f) ? s : log1pf(__expf(s));
}

// ---------------- scan phase 1 ----------------
__global__ __launch_bounds__(512)
void scan1_k(const float* __restrict__ dt, const float* __restrict__ u,
             const float* __restrict__ dbc, const float* __restrict__ Alog,
             float* __restrict__ cP, float* __restrict__ cS)
{
    const int t = threadIdx.x;
    const int dl = t >> 4, s = t & 15;
    const int d = blockIdx.x * 32 + dl;
    const int c = blockIdx.y;
    const float A = -__expf(Alog[d * DS + s]);
    const int l0 = c * CLEN;
    const float* pdt = dt  + (size_t)l0 * DI + d;
    const float* pu  = u   + (size_t)l0 * DI + d;
    const float* pB  = dbc + (size_t)l0 * NXPAD + DTR + s;
    float P = 1.f, S = 0.f;
#pragma unroll 4
    for (int i = 0; i < CLEN; i++) {
        const float dtv = pdt[i * DI];
        const float uv  = pu [i * DI];
        const float Bv  = pB [i * NXPAD];
        const float a = __expf(A * dtv);
        const float b = dtv * Bv * uv;
        P *= a;
        S = a * S + b;
    }
    const int idx = d * DS + s;
    cP[(size_t)c * (DI * DS) + idx] = P;
    cS[(size_t)c * (DI * DS) + idx] = S;
}

// ---------------- scan phase 2 ----------------
__global__ __launch_bounds__(512)
void scan2_k(const float* __restrict__ cP, const float* __restrict__ cS,
             float* __restrict__ hin)
{
    const int idx = blockIdx.x * 512 + threadIdx.x;
    float h = 0.f;
#pragma unroll 4
    for (int c = 0; c < NC; c++) {
        hin[(size_t)c * (DI * DS) + idx] = h;
        h = cP[(size_t)c * (DI * DS) + idx] * h + cS[(size_t)c * (DI * DS) + idx];
    }
}

// ---------------- scan phase 3 ----------------
__global__ __launch_bounds__(512)
void scan3_k(const float* __restrict__ dt, const float* __restrict__ u,
             const float* __restrict__ dbc, const float* __restrict__ Alog,
             const float* __restrict__ hin, const float* __restrict__ xz,
             const float* __restrict__ Dskip, float* __restrict__ yg)
{
    const int t = threadIdx.x;
    const int dl = t >> 4, s = t & 15;
    const int d = blockIdx.x * 32 + dl;
    const int c = blockIdx.y;
    const float A = -__expf(Alog[d * DS + s]);
    const float Dv = Dskip[d];
    const int l0 = c * CLEN;
    const float* pdt = dt  + (size_t)l0 * DI + d;
    const float* pu  = u   + (size_t)l0 * DI + d;
    const float* pB  = dbc + (size_t)l0 * NXPAD + DTR + s;
    const float* pC  = dbc + (size_t)l0 * NXPAD + DTR + DS + s;
    float h = hin[(size_t)c * (DI * DS) + d * DS + s];
#pragma unroll 2
    for (int i = 0; i < CLEN; i++) {
        const float dtv = pdt[i * DI];
        const float uv  = pu [i * DI];
        const float Bv  = pB [i * NXPAD];
        const float Cv  = pC [i * NXPAD];
        const float a = __expf(A * dtv);
        const float b = dtv * Bv * uv;
        h = a * h + b;
        float p = h * Cv;
        p += __shfl_xor_sync(0xffffffffu, p, 8);
        p += __shfl_xor_sync(0xffffffffu, p, 4);
        p += __shfl_xor_sync(0xffffffffu, p, 2);
        p += __shfl_xor_sync(0xffffffffu, p, 1);
        if (s == 0) {
            const int l = l0 + i;
            const float zv  = xz[(size_t)l * (2 * DI) + DI + d];
            const float sig = 1.f / (1.f + __expf(-zv));
            yg[(size_t)l * DI + d] = (p + uv * Dv) * (zv * sig);
        }
    }
}

// ---------------- host launch ----------------
static float* symaddr(const void* sym)
{
    void* p = nullptr;
    cudaGetSymbolAddress(&p, sym);
    return (float*)p;
}

extern "C" void kernel_launch(void* const* d_in, const int* in_sizes, int n_in,
                              void* d_out, int out_size)
{
    const float* x     = (const float*)d_in[0];
    const float* adj   = (const float*)d_in[1];
    const float* gcn_w = (const float*)d_in[2];
    const float* gcn_b = (const float*)d_in[3];
    const float* ln_g  = (const float*)d_in[4];
    const float* ln_b  = (const float*)d_in[5];
    const float* w_in  = (const float*)d_in[6];
    const float* conv_w= (const float*)d_in[7];
    const float* conv_b= (const float*)d_in[8];
    const float* w_xp  = (const float*)d_in[9];
    const float* w_dt  = (const float*)d_in[10];
    const float* b_dt  = (const float*)d_in[11];
    const float* A_log = (const float*)d_in[12];
    const float* D_skip= (const float*)d_in[13];
    const float* w_out = (const float*)d_in[14];
    float* out = (float*)d_out;

    float* t0   = symaddr(g_t0);
    float* part = symaddr(g_part);
    float* h1   = symaddr(g_h1);
    float* hln  = symaddr(g_hln);
    float* xz   = symaddr(g_xz);
    float* u    = symaddr(g_u);
    float* wxpp = symaddr(g_wxpp);
    float* dbc  = symaddr(g_dbc);
    float* dt   = symaddr(g_dt);
    float* cP   = symaddr(g_cP);
    float* cS   = symaddr(g_cS);
    float* hin  = symaddr(g_hin);
    float* yg   = symaddr(g_yg);

    cudaFuncSetAttribute(mma_gemm<false>, cudaFuncAttributeMaxDynamicSharedMemorySize, MMA_SMEM);
    cudaFuncSetAttribute(mma_gemm<true >, cudaFuncAttributeMaxDynamicSharedMemorySize, MMA_SMEM);

    // 0) pad w_xp
    padw_k<<<(DI * NXPAD) / 256, 256>>>(w_xp, wxpp);

    // 1) adj @ x, split-K=4  [K=1024 each]
    mma_gemm<false><<<dim3(DM / BN, LSEQ / BM, 4), 256, MMA_SMEM>>>(
        adj, x, nullptr, part, LSEQ / 4, DM, LSEQ, (size_t)LSEQ * DM);
    reduce_k<<<(LSEQ * DM) / 1024, 256>>>(part, t0, (size_t)LSEQ * DM, 4);

    // 2) h1 = relu(t0 @ gcn_w + b)
    mma_gemm<true ><<<dim3(DM / BN, LSEQ / BM), 256, MMA_SMEM>>>(
        t0, gcn_w, gcn_b, h1, DM, DM, DM, 0);
    // 3) layernorm
    ln_k<<<LSEQ, 256>>>(h1, ln_g, ln_b, hln);
    // 4) xz = hln @ w_in
    mma_gemm<false><<<dim3((2 * DI) / BN, LSEQ / BM), 256, MMA_SMEM>>>(
        hln, w_in, nullptr, xz, DM, 2 * DI, DM, 0);
    // 5) u = silu(conv(xc) + b)
    conv_silu_k<<<(LSEQ * DI) / 256, 256>>>(xz, conv_w, conv_b, u);
    // 6) dbc = u @ w_xp (padded N=64), split-K=4  [K=128 each]
    mma_gemm<false><<<dim3(NXPAD / BN, LSEQ / BM, 4), 256, MMA_SMEM>>>(
        u, wxpp, nullptr, part, DI / 4, NXPAD, DI, (size_t)LSEQ * NXPAD);
    reduce_k<<<(LSEQ * NXPAD) / 1024, 256>>>(part, dbc, (size_t)LSEQ * NXPAD, 4);
    // 7) dt
    dt_k<<<(LSEQ * DI) / 256, 256>>>(dbc, w_dt, b_dt, dt);
    // 8-10) chunked selective scan
    scan1_k<<<dim3(DI / 32, NC), 512>>>(dt, u, dbc, A_log, cP, cS);
    scan2_k<<<(DI * DS) / 512, 512>>>(cP, cS, hin);
    scan3_k<<<dim3(DI / 32, NC), 512>>>(dt, u, dbc, A_log, hin, xz, D_skip, yg);
    // 11) out = yg @ w_out, split-K=2  [K=256 each]
    mma_gemm<false><<<dim3(DM / BN, LSEQ / BM, 2), 256, MMA_SMEM>>>(
        yg, w_out, nullptr, part, DI / 2, DM, DI, (size_t)LSEQ * DM);
    reduce_k<<<(LSEQ * DM) / 1024, 256>>>(part, out, (size_t)LSEQ * DM, 2);
}